// round 7
// baseline (speedup 1.0000x reference)
#include <cuda_runtime.h>
#include <stdint.h>

// StationSelectionAggregator:
//   schedule: [B, WIN, N_ST]  one-hot float32
//   csi:      [B, N_ST, N_SUB, WIN] float32
//   out:      [B, WIN, N_SUB] float32
//   out[b,w,s] = csi[b, t(b,w), s, w]  (exact selection; schedule one-hot).
//
// R7: dense-regular reads. Each warp owns one station plane; every LDG is
// one full 128B line (memcpy-like DRAM stream, 1 wavefront/LDG) instead of
// the gather's ~6 scattered partial lines per LDG. Full 8-plane block staged
// in smem; selection + transpose resolved on the smem->gmem write phase.
// DRAM bytes unchanged (~589 MB measured in all variants) — this targets
// achieved bandwidth only.
#define B_    32
#define NST   8
#define NSUB  256
#define WIN   2048

__global__ __launch_bounds__(256)
void station_select_kernel(const float* __restrict__ sched,
                           const float* __restrict__ csi,
                           float* __restrict__ out) {
    // blockIdx.x : w tile (WIN/32 = 64)  [fastest -> contiguous lines across CTAs]
    // blockIdx.y : s tile (NSUB/32 = 8)
    // blockIdx.z : batch  (32)
    __shared__ float sm[NST][32][33];   // [plane][s_local][w_local], +1 pad (~33.8 KB)
    __shared__ int   tw[32];            // selected station per w

    const int b   = blockIdx.z;
    const int w0  = blockIdx.x * 32;
    const int s0  = blockIdx.y * 32;
    const int tid = threadIdx.x;        // 0..255
    const int tx  = tid & 31;           // lane -> w_local on loads
    const int ty  = tid >> 5;           // warp -> station plane (8 warps = 8 planes)

    // --- station index per w (exact: one-hot values are 0.0/1.0) ---
    if (tid < 32) {
        const float4* sp = reinterpret_cast<const float4*>(
            sched + ((size_t)b * WIN + (size_t)(w0 + tid)) * NST);
        const float4 a = sp[0];
        const float4 c = sp[1];
        const float tf = a.y + 2.f * a.z + 3.f * a.w +
                         4.f * c.x + 5.f * c.y + 6.f * c.z + 7.f * c.w;
        tw[tid] = (int)(tf + 0.5f);
    }

    // --- dense loads: warp ty streams plane ty; each LDG = one 128B line ---
    // Independent of tw -> no serialization behind the schedule decode.
    const float* p = csi
        + ((size_t)(b * NST + ty) * NSUB + (size_t)s0) * WIN
        + (size_t)(w0 + tx);
#pragma unroll
    for (int r = 0; r < 32; r++) {
        // STS bank = (r + tx) & 31 : conflict-free (plane offset 1056 == 0 mod 32)
        sm[ty][r][tx] = p[(size_t)r * WIN];
    }
    __syncthreads();

    // --- select + transpose on the way out: coalesced along s ---
#pragma unroll
    for (int rr = 0; rr < 4; rr++) {
        const int wl = ty + rr * 8;          // w_local 0..31
        const int t  = tw[wl];               // uniform across the warp
        // LDS bank = (tx + wl) & 31 : conflict-free
        out[((size_t)b * WIN + (size_t)(w0 + wl)) * NSUB + (size_t)(s0 + tx)]
            = sm[t][tx][wl];
    }
}

extern "C" void kernel_launch(void* const* d_in, const int* in_sizes, int n_in,
                              void* d_out, int out_size) {
    const float* sched = (const float*)d_in[0];
    const float* csi   = (const float*)d_in[1];
    if (n_in >= 2 && in_sizes[0] != 524288) {   // schedule = 32*2048*8 elems
        sched = (const float*)d_in[1];
        csi   = (const float*)d_in[0];
    }
    float* out = (float*)d_out;

    dim3 block(256, 1, 1);
    dim3 grid(WIN / 32, NSUB / 32, B_);
    station_select_kernel<<<grid, block>>>(sched, csi, out);
}

// round 8
// speedup vs baseline: 1.2579x; 1.2579x over previous
#include <cuda_runtime.h>
#include <stdint.h>

// StationSelectionAggregator:
//   schedule: [B, WIN, N_ST]  one-hot float32
//   csi:      [B, N_ST, N_SUB, WIN] float32
//   out:      [B, WIN, N_SUB] float32
//   out[b,w,s] = csi[b, t(b,w), s, w]  (exact selection; schedule one-hot).
//
// Final structure = R1 (best of 7 variants, 6.83 TB/s) with the schedule
// stage inlined per-lane: no tw smem, no pre-gather barrier, gather LDGs
// issue immediately at CTA start. All previously-regressing ideas excluded
// (cache hints, persistence, dense reads, wide tiles, big smem staging).
#define B_    32
#define NST   8
#define NSUB  256
#define WIN   2048

__global__ __launch_bounds__(256)
void station_select_kernel(const float* __restrict__ sched,
                           const float* __restrict__ csi,
                           float* __restrict__ out) {
    // blockIdx.x : w tile (WIN/32 = 64)  [fastest -> contiguous lines across CTAs]
    // blockIdx.y : s tile (NSUB/32 = 8)
    // blockIdx.z : batch  (32)
    __shared__ float tile[32][33];   // [s_local][w_local], +1 pad

    const int b   = blockIdx.z;
    const int w0  = blockIdx.x * 32;
    const int s0  = blockIdx.y * 32;
    const int tid = threadIdx.x;     // 0..255
    const int tx  = tid & 31;
    const int ty  = tid >> 5;        // 0..7

    // --- per-lane station decode (exact: one-hot values are 0.0/1.0) ---
    // Redundant across the 8 warps but L1-resident; removes the tw-smem
    // stage and its barrier so the gather issues immediately.
    const float4* sp = reinterpret_cast<const float4*>(
        sched + ((size_t)b * WIN + (size_t)(w0 + tx)) * NST);
    const float4 a = __ldg(sp);
    const float4 c = __ldg(sp + 1);
    const float tf = a.y + 2.f * a.z + 3.f * a.w +
                     4.f * c.x + 5.f * c.y + 6.f * c.z + 7.f * c.w;
    const int t = (int)(tf + 0.5f);

    // --- gather: coalesced along w (tx); 4 independent LDGs batched ---
    const float* p = csi + ((size_t)(b * NST + t) * NSUB + (size_t)s0) * WIN
                         + (size_t)(w0 + tx);
    float v[4];
#pragma unroll
    for (int r = 0; r < 4; r++)
        v[r] = p[(size_t)(ty + r * 8) * WIN];

    // smem stage: bank = (sl + tx) & 31 -> conflict-free
#pragma unroll
    for (int r = 0; r < 4; r++)
        tile[ty + r * 8][tx] = v[r];
    __syncthreads();

    // --- transposed writes: coalesced along s (tx) ---
#pragma unroll
    for (int r = 0; r < 4; r++) {
        const int wl = ty + r * 8;   // w_local
        // LDS bank = (tx + wl) & 31 -> conflict-free
        out[((size_t)b * WIN + (size_t)(w0 + wl)) * NSUB + (size_t)(s0 + tx)]
            = tile[tx][wl];
    }
}

extern "C" void kernel_launch(void* const* d_in, const int* in_sizes, int n_in,
                              void* d_out, int out_size) {
    const float* sched = (const float*)d_in[0];
    const float* csi   = (const float*)d_in[1];
    if (n_in >= 2 && in_sizes[0] != 524288) {   // schedule = 32*2048*8 elems
        sched = (const float*)d_in[1];
        csi   = (const float*)d_in[0];
    }
    float* out = (float*)d_out;

    dim3 block(256, 1, 1);
    dim3 grid(WIN / 32, NSUB / 32, B_);
    station_select_kernel<<<grid, block>>>(sched, csi, out);
}